// round 1
// baseline (speedup 1.0000x reference)
#include <cuda_runtime.h>
#include <cstdint>

// B=512, T=256, NE=384, H=64
// Scratch (static __device__ arrays -- no allocation)
__device__ float g_q [512*256*64];   // [b][t][h]
__device__ float g_kT[512*64*256];   // [b][h][t]  (transposed at GEMM epilogue)
__device__ float g_vT[512*64*256];   // [b][h][t]

// ---------- packed f32x2 helpers (FFMA2: 2x fp32 FMA throughput on sm_103a) ----------
__device__ __forceinline__ unsigned long long pk2(float lo, float hi) {
    unsigned long long r;
    asm("mov.b64 %0, {%1, %2};" : "=l"(r) : "f"(lo), "f"(hi));
    return r;
}
__device__ __forceinline__ unsigned long long ffma2(unsigned long long a,
                                                    unsigned long long b,
                                                    unsigned long long c) {
    unsigned long long d;
    asm("fma.rn.f32x2 %0, %1, %2, %3;" : "=l"(d) : "l"(a), "l"(b), "l"(c));
    return d;
}
__device__ __forceinline__ float2 upk2(unsigned long long v) {
    float2 r;
    asm("mov.b64 {%0, %1}, %2;" : "=f"(r.x), "=f"(r.y) : "l"(v));
    return r;
}

// ---------------- Fused QKV projection ----------------
// Block computes 64 token-rows x (3 x 64) outputs. K-tiles of 32.
// x tile stored transposed [kk][t] (pitch 68), W tiles [m][kk][c] (pitch 68):
// both give aligned float4 smem loads in the inner loop.
__global__ __launch_bounds__(256) void qkv_kernel(
    const float* __restrict__ x, const float* __restrict__ Wk,
    const float* __restrict__ Wq, const float* __restrict__ Wv) {
  __shared__ float sm[8704];          // 34.8 KB
  float* xs = sm;                     // [32][68] transposed
  float* ws = sm + 2176;              // [3][32][68]  m: 0=q, 1=k, 2=v
  const int tid = threadIdx.x;
  const int tx = tid & 15, ty = tid >> 4;
  const int m0 = blockIdx.x * 64;     // 2048 blocks; never crosses a batch (64 | 256)

  unsigned long long acc[3][4][2];
  #pragma unroll
  for (int m = 0; m < 3; m++)
    #pragma unroll
    for (int i = 0; i < 4; i++) { acc[m][i][0] = 0ull; acc[m][i][1] = 0ull; }

  for (int kt = 0; kt < 384; kt += 32) {
    // x tile: coalesced global read, transposed smem write
    for (int i = tid; i < 2048; i += 256) {
      int c = i & 31, r = i >> 5;
      xs[c*68 + r] = x[(long)(m0 + r)*384 + kt + c];
    }
    // W tiles (all three)
    for (int i = tid; i < 3*2048; i += 256) {
      int mm = i >> 11, j = i & 2047, r = j >> 6, c = j & 63;
      const float* W = (mm == 0) ? Wq : (mm == 1 ? Wk : Wv);
      ws[mm*2176 + r*68 + c] = W[(kt + r)*64 + c];
    }
    __syncthreads();

    #pragma unroll 8
    for (int kk = 0; kk < 32; kk++) {
      float4 a = *(const float4*)(xs + kk*68 + ty*4);
      unsigned long long ap[4] = {pk2(a.x,a.x), pk2(a.y,a.y), pk2(a.z,a.z), pk2(a.w,a.w)};
      #pragma unroll
      for (int m = 0; m < 3; m++) {
        float4 b = *(const float4*)(ws + m*2176 + kk*68 + tx*4);
        unsigned long long b01 = pk2(b.x, b.y), b23 = pk2(b.z, b.w);
        #pragma unroll
        for (int i = 0; i < 4; i++) {
          acc[m][i][0] = ffma2(ap[i], b01, acc[m][i][0]);
          acc[m][i][1] = ffma2(ap[i], b23, acc[m][i][1]);
        }
      }
    }
    __syncthreads();
  }

  // q: direct row-major write (coalesced float4)
  #pragma unroll
  for (int i = 0; i < 4; i++) {
    float2 lo = upk2(acc[0][i][0]), hi = upk2(acc[0][i][1]);
    float4 v = make_float4(lo.x, lo.y, hi.x, hi.y);
    *(float4*)(g_q + (long)(m0 + ty*4 + i)*64 + tx*4) = v;
  }

  // k, v: stage in smem [t][h] (pitch 65, conflict-free readback), write transposed [b][h][t]
  const int b  = m0 >> 8;
  const int t0 = m0 & 255;
  float* stage = sm;                  // reuse (64*65 = 4160 floats)
  for (int m = 1; m <= 2; m++) {
    __syncthreads();
    #pragma unroll
    for (int i = 0; i < 4; i++) {
      float2 lo = upk2(acc[m][i][0]), hi = upk2(acc[m][i][1]);
      float* s = stage + (ty*4 + i)*65 + tx*4;
      s[0] = lo.x; s[1] = lo.y; s[2] = hi.x; s[3] = hi.y;
    }
    __syncthreads();
    float* dst = (m == 1) ? g_kT : g_vT;
    for (int i = tid; i < 4096; i += 256) {
      int t = i & 63, h = i >> 6;                   // consecutive tid -> consecutive t: coalesced
      dst[(long)b*16384 + h*256 + t0 + t] = stage[t*65 + h];
    }
  }
}

// ---------------- Causal attention: one block per batch ----------------
// Kt/Vt already transposed in global -> straight coalesced float4 copy into smem.
__global__ __launch_bounds__(256) void attn_kernel(float* __restrict__ out) {
  extern __shared__ float smem[];
  float* Kt = smem;                    // [64][256]
  float* Vt = smem + 16384;            // [64][256]
  float* Ps = smem + 32768;            // [8][256]   per-warp unnormalized probs
  float* qs = smem + 32768 + 2048;     // [8][64]    per-warp q row (pre-scaled)
  const int b = blockIdx.x;
  const int tid = threadIdx.x, lane = tid & 31, w = tid >> 5;

  {
    const float4* Kg = (const float4*)(g_kT + (long)b*16384);
    const float4* Vg = (const float4*)(g_vT + (long)b*16384);
    float4* K4 = (float4*)Kt;
    float4* V4 = (float4*)Vt;
    for (int i = tid; i < 4096; i += 256) { K4[i] = Kg[i]; V4[i] = Vg[i]; }
  }
  __syncthreads();

  float* Pw = Ps + w*256;
  float* qw = qs + w*64;
  const float4* P4 = (const float4*)Pw;

  for (int r = w; r < 256; r += 8) {
    const float* qrow = g_q + ((long)b*256 + r)*64;
    qw[lane]      = qrow[lane]      * 0.125f;   // fold H^-0.5 into q
    qw[lane + 32] = qrow[lane + 32] * 0.125f;
    __syncwarp();

    const int t = r;   // causal bound: keys 0..t
    // score phase: lane owns keys {4*lane..4*lane+3} (+128 in pass 1)
    float4 s0 = make_float4(0.f,0.f,0.f,0.f);
    float4 s1 = make_float4(0.f,0.f,0.f,0.f);
    if (t >= 128) {
      #pragma unroll 4
      for (int h = 0; h < 64; h++) {
        float qh = qw[h];
        const float4* kr = (const float4*)(Kt + (h << 8));
        float4 k0 = kr[lane], k1 = kr[lane + 32];
        s0.x = fmaf(qh,k0.x,s0.x); s0.y = fmaf(qh,k0.y,s0.y);
        s0.z = fmaf(qh,k0.z,s0.z); s0.w = fmaf(qh,k0.w,s0.w);
        s1.x = fmaf(qh,k1.x,s1.x); s1.y = fmaf(qh,k1.y,s1.y);
        s1.z = fmaf(qh,k1.z,s1.z); s1.w = fmaf(qh,k1.w,s1.w);
      }
    } else {
      #pragma unroll 4
      for (int h = 0; h < 64; h++) {
        float qh = qw[h];
        const float4* kr = (const float4*)(Kt + (h << 8));
        float4 k0 = kr[lane];
        s0.x = fmaf(qh,k0.x,s0.x); s0.y = fmaf(qh,k0.y,s0.y);
        s0.z = fmaf(qh,k0.z,s0.z); s0.w = fmaf(qh,k0.w,s0.w);
      }
    }

    // softmax (causal mask -> p=0 for j>t)
    const int j0 = lane * 4;
    float sc[8] = {s0.x,s0.y,s0.z,s0.w, s1.x,s1.y,s1.z,s1.w};
    float mx = -1e30f;
    #pragma unroll
    for (int i = 0; i < 4; i++) if (j0 + i <= t)       mx = fmaxf(mx, sc[i]);
    #pragma unroll
    for (int i = 0; i < 4; i++) if (128 + j0 + i <= t) mx = fmaxf(mx, sc[4+i]);
    #pragma unroll
    for (int o = 16; o > 0; o >>= 1) mx = fmaxf(mx, __shfl_xor_sync(0xffffffffu, mx, o));

    float p[8]; float ls = 0.f;
    #pragma unroll
    for (int i = 0; i < 4; i++) { p[i]   = (j0 + i <= t)       ? __expf(sc[i]   - mx) : 0.f; ls += p[i]; }
    #pragma unroll
    for (int i = 0; i < 4; i++) { p[4+i] = (128 + j0 + i <= t) ? __expf(sc[4+i] - mx) : 0.f; ls += p[4+i]; }
    #pragma unroll
    for (int o = 16; o > 0; o >>= 1) ls += __shfl_xor_sync(0xffffffffu, ls, o);

    ((float4*)Pw)[lane] = make_float4(p[0],p[1],p[2],p[3]);
    if (t >= 128) ((float4*)Pw)[lane + 32] = make_float4(p[4],p[5],p[6],p[7]);
    __syncwarp();

    // out phase: lane owns h=lane and h=lane+32
    float acc0 = 0.f, acc1 = 0.f;
    const float4* v0row = (const float4*)(Vt + (lane << 8));
    const float4* v1row = (const float4*)(Vt + ((lane + 32) << 8));
    const int nch = (t >> 2) + 1;
    #pragma unroll 4
    for (int c = 0; c < nch; c++) {
      float4 pp = P4[c];
      float4 va = v0row[c];
      float4 vb = v1row[c];
      acc0 += pp.x*va.x + pp.y*va.y + pp.z*va.z + pp.w*va.w;
      acc1 += pp.x*vb.x + pp.y*vb.y + pp.z*vb.z + pp.w*vb.w;
    }
    float inv = 1.0f / ls;
    float* orow = out + ((long)b*256 + r)*64;
    orow[lane]      = acc0 * inv;
    orow[lane + 32] = acc1 * inv;
    __syncwarp();
  }
}

extern "C" void kernel_launch(void* const* d_in, const int* in_sizes, int n_in,
                              void* d_out, int out_size) {
  const float* x  = (const float*)d_in[0];
  const float* Wk = (const float*)d_in[1];
  const float* Wq = (const float*)d_in[2];
  const float* Wv = (const float*)d_in[3];
  float* out = (float*)d_out;
  (void)in_sizes; (void)n_in; (void)out_size;

  cudaFuncSetAttribute(attn_kernel, cudaFuncAttributeMaxDynamicSharedMemorySize, 141312);

  qkv_kernel<<<2048, 256>>>(x, Wk, Wq, Wv);
  attn_kernel<<<512, 256, 141312>>>(out);
}

// round 4
// speedup vs baseline: 4.1325x; 4.1325x over previous
#include <cuda_runtime.h>
#include <cstdint>

// B=512, T=256, NE=384, H=64
__device__ float g_q [512*256*64];   // [b][t][h]
__device__ float g_kT[512*64*256];   // [b][h][t]
__device__ float g_v [512*256*64];   // [b][t][h]
__device__ float g_WT[192*384];      // [n][k]  n: 0-63 Wq, 64-127 Wk, 128-191 Wv (tf32-rounded)

static __device__ __forceinline__ float to_tf32(float x){
  float r; asm("cvt.rna.tf32.f32 %0, %1;" : "=f"(r) : "f"(x)); return r;
}
static __device__ __forceinline__ unsigned long long pk2(float lo, float hi){
  unsigned long long r; asm("mov.b64 %0, {%1, %2};" : "=l"(r) : "f"(lo), "f"(hi)); return r;
}
static __device__ __forceinline__ unsigned long long ffma2(unsigned long long a,
                                                           unsigned long long b,
                                                           unsigned long long c){
  unsigned long long d; asm("fma.rn.f32x2 %0, %1, %2, %3;" : "=l"(d) : "l"(a), "l"(b), "l"(c));
  return d;
}
static __device__ __forceinline__ float2 upk2(unsigned long long v){
  float2 r; asm("mov.b64 {%0, %1}, %2;" : "=f"(r.x), "=f"(r.y) : "l"(v)); return r;
}
static __device__ __forceinline__ void mma16n8k8(float* d, const uint32_t* a, const uint32_t* b){
  asm volatile(
    "mma.sync.aligned.m16n8k8.row.col.f32.tf32.tf32.f32 "
    "{%0,%1,%2,%3}, {%4,%5,%6,%7}, {%8,%9}, {%0,%1,%2,%3};"
    : "+f"(d[0]), "+f"(d[1]), "+f"(d[2]), "+f"(d[3])
    : "r"(a[0]), "r"(a[1]), "r"(a[2]), "r"(a[3]), "r"(b[0]), "r"(b[1]));
}

// ---------------- W transpose + tf32 round (one-time, tiny) ----------------
__global__ void wt_kernel(const float* __restrict__ Wk, const float* __restrict__ Wq,
                          const float* __restrict__ Wv){
  const int n = blockIdx.x;
  const int c = n & 63;
  const float* W = (n < 64) ? Wq : (n < 128 ? Wk : Wv);
  for (int k = threadIdx.x; k < 384; k += 128)
    g_WT[n*384 + k] = to_tf32(W[k*64 + c]);
}

// ---------------- QKV projection via mma.sync tf32 (sm_80-class, no 'a' gate) ------
// D[128tok, 192] = x_tile[128, 384] @ WT^T; N: 0-63 q, 64-127 k, 128-191 v.
// 8 warps = 2(M) x 4(N); warp tile 64 x 48 = 4 m-frags x 6 n-frags of m16n8k8.
__global__ __launch_bounds__(256) void qkv_mma(const float* __restrict__ x){
  __shared__ float As[16][136];   // [k][m]  pitch 136 -> frag banks (8*tig+g)%32 distinct
  __shared__ float Bs[16][200];   // [k][n]  pitch 200 -> same property
  const int tid = threadIdx.x, lane = tid & 31, warp = tid >> 5;
  const int g = lane >> 2, tig = lane & 3;
  const int wm = warp >> 2, wn = warp & 3;       // 2 x 4 warp grid
  const int m0 = blockIdx.x * 128;

  float C[4][6][4];
  #pragma unroll
  for (int mf = 0; mf < 4; mf++)
    #pragma unroll
    for (int nf = 0; nf < 6; nf++)
      { C[mf][nf][0]=0.f; C[mf][nf][1]=0.f; C[mf][nf][2]=0.f; C[mf][nf][3]=0.f; }

  for (int kt = 0; kt < 384; kt += 16){
    // A tile: 128 rows x 16 k (tf32-rounded), stored transposed [k][m]
    #pragma unroll
    for (int it = 0; it < 2; it++){
      int idx = tid + 256*it, r = idx >> 2, c4 = idx & 3;
      float4 v = *(const float4*)(x + (size_t)(m0 + r)*384 + kt + c4*4);
      As[c4*4+0][r] = to_tf32(v.x); As[c4*4+1][r] = to_tf32(v.y);
      As[c4*4+2][r] = to_tf32(v.z); As[c4*4+3][r] = to_tf32(v.w);
    }
    // B tile: 192 n-rows x 16 k (already tf32), stored [k][n]
    #pragma unroll
    for (int it = 0; it < 3; it++){
      int idx = tid + 256*it, n = idx >> 2, c4 = idx & 3;
      float4 v = *(const float4*)(g_WT + n*384 + kt + c4*4);
      Bs[c4*4+0][n] = v.x; Bs[c4*4+1][n] = v.y;
      Bs[c4*4+2][n] = v.z; Bs[c4*4+3][n] = v.w;
    }
    __syncthreads();

    #pragma unroll
    for (int ks = 0; ks < 2; ks++){
      const int k0 = ks*8;
      uint32_t a[4][4];
      #pragma unroll
      for (int mf = 0; mf < 4; mf++){
        const int mr = wm*64 + mf*16;
        a[mf][0] = __float_as_uint(As[k0+tig  ][mr+g  ]);
        a[mf][1] = __float_as_uint(As[k0+tig  ][mr+g+8]);
        a[mf][2] = __float_as_uint(As[k0+tig+4][mr+g  ]);
        a[mf][3] = __float_as_uint(As[k0+tig+4][mr+g+8]);
      }
      uint32_t b[6][2];
      #pragma unroll
      for (int nf = 0; nf < 6; nf++){
        const int nb = wn*48 + nf*8;
        b[nf][0] = __float_as_uint(Bs[k0+tig  ][nb+g]);
        b[nf][1] = __float_as_uint(Bs[k0+tig+4][nb+g]);
      }
      #pragma unroll
      for (int mf = 0; mf < 4; mf++)
        #pragma unroll
        for (int nf = 0; nf < 6; nf++)
          mma16n8k8(C[mf][nf], a[mf], b[nf]);
    }
    __syncthreads();
  }

  // Epilogue: frag (row m, cols n..n+1). q/v straight [t][h] float2; k transposed [b][h][t].
  const int bb = m0 >> 8;
  #pragma unroll
  for (int mf = 0; mf < 4; mf++){
    const int mlo = m0 + wm*64 + mf*16 + g;
    #pragma unroll
    for (int nf = 0; nf < 6; nf++){
      const int n = wn*48 + nf*8 + 2*tig;
      const int id = n >> 6, h = n & 63;
      if (id == 1){   // k -> g_kT[b][h][t]
        float* base = g_kT + (size_t)bb*16384;
        base[(h  )*256 + (mlo    & 255)] = C[mf][nf][0];
        base[(h+1)*256 + (mlo    & 255)] = C[mf][nf][1];
        base[(h  )*256 + ((mlo+8)& 255)] = C[mf][nf][2];
        base[(h+1)*256 + ((mlo+8)& 255)] = C[mf][nf][3];
      } else {
        float* dst = (id == 0) ? g_q : g_v;
        *(float2*)(dst + (size_t)(mlo    )*64 + h) = make_float2(C[mf][nf][0], C[mf][nf][1]);
        *(float2*)(dst + (size_t)(mlo + 8)*64 + h) = make_float2(C[mf][nf][2], C[mf][nf][3]);
      }
    }
  }
}

// ---------------- Causal attention (one CTA per batch, 512 threads) ----------------
// K transposed [h][t] (conflict-free score reads); V straight [t][h] (conflict-free
// out-phase reads -- fixes the 32-way bank conflict that dominated v1).
__global__ __launch_bounds__(512) void attn2(float* __restrict__ out){
  extern __shared__ float sm[];
  float* Kt = sm;                      // [64][256]
  float* Vs = sm + 16384;              // [256][64]
  float* Ps = sm + 32768;              // [16 warps][4 rows][256]
  float* qs = sm + 49152;              // [16 warps][4 rows][64]
  const int b = blockIdx.x;
  const int tid = threadIdx.x, lane = tid & 31, w = tid >> 5;

  {
    const float4* Kg = (const float4*)(g_kT + (size_t)b*16384);
    const float4* Vg = (const float4*)(g_v  + (size_t)b*16384);
    float4* K4 = (float4*)Kt; float4* V4 = (float4*)Vs;
    #pragma unroll
    for (int j = 0; j < 8; j++){ int i = tid + 512*j; K4[i] = Kg[i]; V4[i] = Vg[i]; }
  }
  __syncthreads();

  float*  Pw  = Ps + w*1024;
  float*  qw  = qs + w*256;
  float4* Pw4 = (float4*)Pw;

  for (int pass = 0; pass < 4; pass++){
    const int base = pass*64 + w*4;    // 4 consecutive rows per warp
    #pragma unroll
    for (int i = 0; i < 4; i++){
      const float* qr = g_q + ((size_t)b*256 + base + i)*64;
      qw[i*64 + lane]      = qr[lane]      * 0.125f;   // fold H^-0.5
      qw[i*64 + lane + 32] = qr[lane + 32] * 0.125f;
    }
    __syncwarp();

    const bool hi = (base >= 128);
    unsigned long long s2[4][4];
    #pragma unroll
    for (int i = 0; i < 4; i++){ s2[i][0]=0; s2[i][1]=0; s2[i][2]=0; s2[i][3]=0; }

    // score: lane owns keys {4l..4l+3} (+128 when hi); 4 rows share every K load
    for (int h = 0; h < 64; h++){
      const float4* kr = (const float4*)(Kt + (h << 8));
      float4 k0 = kr[lane];
      unsigned long long ka = pk2(k0.x, k0.y), kb = pk2(k0.z, k0.w);
      unsigned long long kc = 0, kd = 0;
      if (hi){ float4 k1 = kr[lane + 32]; kc = pk2(k1.x, k1.y); kd = pk2(k1.z, k1.w); }
      #pragma unroll
      for (int i = 0; i < 4; i++){
        float qh = qw[i*64 + h];
        unsigned long long qq = pk2(qh, qh);
        s2[i][0] = ffma2(qq, ka, s2[i][0]);
        s2[i][1] = ffma2(qq, kb, s2[i][1]);
        if (hi){ s2[i][2] = ffma2(qq, kc, s2[i][2]); s2[i][3] = ffma2(qq, kd, s2[i][3]); }
      }
    }

    // softmax per row
    float inv[4];
    #pragma unroll
    for (int i = 0; i < 4; i++){
      const int t = base + i, j0 = lane*4;
      float2 a0 = upk2(s2[i][0]), a1 = upk2(s2[i][1]);
      float sc[8] = {a0.x, a0.y, a1.x, a1.y, 0.f, 0.f, 0.f, 0.f};
      if (hi){
        float2 a2 = upk2(s2[i][2]), a3 = upk2(s2[i][3]);
        sc[4] = a2.x; sc[5] = a2.y; sc[6] = a3.x; sc[7] = a3.y;
      }
      float mx = -1e30f;
      #pragma unroll
      for (int u = 0; u < 4; u++) if (j0 + u <= t) mx = fmaxf(mx, sc[u]);
      if (hi){
        #pragma unroll
        for (int u = 0; u < 4; u++) if (128 + j0 + u <= t) mx = fmaxf(mx, sc[4+u]);
      }
      #pragma unroll
      for (int o = 16; o; o >>= 1) mx = fmaxf(mx, __shfl_xor_sync(0xffffffffu, mx, o));

      float p[8]; float ls = 0.f;
      #pragma unroll
      for (int u = 0; u < 4; u++){ p[u] = (j0 + u <= t) ? __expf(sc[u] - mx) : 0.f; ls += p[u]; }
      if (hi){
        #pragma unroll
        for (int u = 0; u < 4; u++){
          p[4+u] = (128 + j0 + u <= t) ? __expf(sc[4+u] - mx) : 0.f; ls += p[4+u];
        }
      } else { p[4]=p[5]=p[6]=p[7]=0.f; }
      #pragma unroll
      for (int o = 16; o; o >>= 1) ls += __shfl_xor_sync(0xffffffffu, ls, o);
      inv[i] = 1.0f / ls;
      Pw4[i*64 + lane] = make_float4(p[0], p[1], p[2], p[3]);
      if (hi) Pw4[i*64 + 32 + lane] = make_float4(p[4], p[5], p[6], p[7]);
    }
    __syncwarp();

    // out: lane owns h={lane, lane+32}; P broadcast (1 phase), V conflict-free
    unsigned long long o2[4] = {0ull, 0ull, 0ull, 0ull};
    const int cmax = base >> 2;
    for (int c = 0; c <= cmax; c++){
      unsigned long long vv[4];
      #pragma unroll
      for (int jj = 0; jj < 4; jj++){
        const float* vr = Vs + ((c*4 + jj) << 6);
        vv[jj] = pk2(vr[lane], vr[lane + 32]);
      }
      #pragma unroll
      for (int i = 0; i < 4; i++){
        float4 pp = Pw4[i*64 + c];
        o2[i] = ffma2(pk2(pp.x, pp.x), vv[0], o2[i]);
        o2[i] = ffma2(pk2(pp.y, pp.y), vv[1], o2[i]);
        o2[i] = ffma2(pk2(pp.z, pp.z), vv[2], o2[i]);
        o2[i] = ffma2(pk2(pp.w, pp.w), vv[3], o2[i]);
      }
    }
    #pragma unroll
    for (int i = 0; i < 4; i++){
      float2 o = upk2(o2[i]);
      float* orow = out + ((size_t)b*256 + base + i)*64;
      orow[lane]      = o.x * inv[i];
      orow[lane + 32] = o.y * inv[i];
    }
    __syncwarp();
  }
}

extern "C" void kernel_launch(void* const* d_in, const int* in_sizes, int n_in,
                              void* d_out, int out_size) {
  const float* x  = (const float*)d_in[0];
  const float* Wk = (const float*)d_in[1];
  const float* Wq = (const float*)d_in[2];
  const float* Wv = (const float*)d_in[3];
  float* out = (float*)d_out;
  (void)in_sizes; (void)n_in; (void)out_size;

  cudaFuncSetAttribute(attn2, cudaFuncAttributeMaxDynamicSharedMemorySize, 212992);

  wt_kernel<<<192, 128>>>(Wk, Wq, Wv);
  qkv_mma<<<1024, 256>>>(x);
  attn2<<<512, 512, 212992>>>(out);
}

// round 5
// speedup vs baseline: 7.3049x; 1.7676x over previous
#include <cuda_runtime.h>
#include <cstdint>

// B=512, T=256, NE=384, H=64
__device__ float g_q [512*256*64];   // [b][t][h]
__device__ float g_k [512*256*64];   // [b][t][h]
__device__ float g_vT[512*64*256];   // [b][h][t]
__device__ float g_WT[192*384];      // [n][k]  n: 0-63 Wq, 64-127 Wk, 128-191 Wv (tf32)

static __device__ __forceinline__ float to_tf32(float x){
  float r; asm("cvt.rna.tf32.f32 %0, %1;" : "=f"(r) : "f"(x)); return r;
}
static __device__ __forceinline__ void mma16n8k8(float* d, const uint32_t* a, const uint32_t* b){
  asm volatile(
    "mma.sync.aligned.m16n8k8.row.col.f32.tf32.tf32.f32 "
    "{%0,%1,%2,%3}, {%4,%5,%6,%7}, {%8,%9}, {%0,%1,%2,%3};"
    : "+f"(d[0]), "+f"(d[1]), "+f"(d[2]), "+f"(d[3])
    : "r"(a[0]), "r"(a[1]), "r"(a[2]), "r"(a[3]), "r"(b[0]), "r"(b[1]));
}

// ---------------- W transpose + tf32 round ----------------
__global__ void wt_kernel(const float* __restrict__ Wk, const float* __restrict__ Wq,
                          const float* __restrict__ Wv){
  const int n = blockIdx.x;
  const int c = n & 63;
  const float* W = (n < 64) ? Wq : (n < 128 ? Wk : Wv);
  for (int k = threadIdx.x; k < 384; k += 128)
    g_WT[n*384 + k] = to_tf32(W[k*64 + c]);
}

// ---------------- QKV projection via mma.sync tf32, software-pipelined ----------------
__global__ __launch_bounds__(256) void qkv_mma(const float* __restrict__ x){
  __shared__ float As[16][136];   // [k][m]
  __shared__ float Bs[16][200];   // [k][n]
  const int tid = threadIdx.x, lane = tid & 31, warp = tid >> 5;
  const int g = lane >> 2, tig = lane & 3;
  const int wm = warp >> 2, wn = warp & 3;
  const int m0 = blockIdx.x * 128;

  float C[4][6][4];
  #pragma unroll
  for (int mf = 0; mf < 4; mf++)
    #pragma unroll
    for (int nf = 0; nf < 6; nf++)
      { C[mf][nf][0]=0.f; C[mf][nf][1]=0.f; C[mf][nf][2]=0.f; C[mf][nf][3]=0.f; }

  const int ar0 = tid >> 2,        ac0 = tid & 3;
  const int ar1 = (tid+256) >> 2,  ac1 = tid & 3;
  const int br0 = tid >> 2,        bc0 = tid & 3;
  const int br1 = (tid+256) >> 2,  bc1 = tid & 3;
  const int br2 = (tid+512) >> 2,  bc2 = tid & 3;

  float4 ra0, ra1, rb0, rb1, rb2;
  // prefetch tile 0
  ra0 = *(const float4*)(x + (size_t)(m0 + ar0)*384 + ac0*4);
  ra1 = *(const float4*)(x + (size_t)(m0 + ar1)*384 + ac1*4);
  rb0 = *(const float4*)(g_WT + br0*384 + bc0*4);
  rb1 = *(const float4*)(g_WT + br1*384 + bc1*4);
  rb2 = *(const float4*)(g_WT + br2*384 + bc2*4);

  for (int kt = 0; kt < 384; kt += 16){
    // commit prefetched tile to smem
    As[ac0*4+0][ar0] = to_tf32(ra0.x); As[ac0*4+1][ar0] = to_tf32(ra0.y);
    As[ac0*4+2][ar0] = to_tf32(ra0.z); As[ac0*4+3][ar0] = to_tf32(ra0.w);
    As[ac1*4+0][ar1] = to_tf32(ra1.x); As[ac1*4+1][ar1] = to_tf32(ra1.y);
    As[ac1*4+2][ar1] = to_tf32(ra1.z); As[ac1*4+3][ar1] = to_tf32(ra1.w);
    Bs[bc0*4+0][br0] = rb0.x; Bs[bc0*4+1][br0] = rb0.y;
    Bs[bc0*4+2][br0] = rb0.z; Bs[bc0*4+3][br0] = rb0.w;
    Bs[bc1*4+0][br1] = rb1.x; Bs[bc1*4+1][br1] = rb1.y;
    Bs[bc1*4+2][br1] = rb1.z; Bs[bc1*4+3][br1] = rb1.w;
    Bs[bc2*4+0][br2] = rb2.x; Bs[bc2*4+1][br2] = rb2.y;
    Bs[bc2*4+2][br2] = rb2.z; Bs[bc2*4+3][br2] = rb2.w;
    __syncthreads();

    if (kt < 368){  // prefetch next tile; LDGs fly during the MMAs below
      const int kn = kt + 16;
      ra0 = *(const float4*)(x + (size_t)(m0 + ar0)*384 + kn + ac0*4);
      ra1 = *(const float4*)(x + (size_t)(m0 + ar1)*384 + kn + ac1*4);
      rb0 = *(const float4*)(g_WT + br0*384 + kn + bc0*4);
      rb1 = *(const float4*)(g_WT + br1*384 + kn + bc1*4);
      rb2 = *(const float4*)(g_WT + br2*384 + kn + bc2*4);
    }

    #pragma unroll
    for (int ks = 0; ks < 2; ks++){
      const int k0 = ks*8;
      uint32_t a[4][4];
      #pragma unroll
      for (int mf = 0; mf < 4; mf++){
        const int mr = wm*64 + mf*16;
        a[mf][0] = __float_as_uint(As[k0+tig  ][mr+g  ]);
        a[mf][1] = __float_as_uint(As[k0+tig  ][mr+g+8]);
        a[mf][2] = __float_as_uint(As[k0+tig+4][mr+g  ]);
        a[mf][3] = __float_as_uint(As[k0+tig+4][mr+g+8]);
      }
      uint32_t b[6][2];
      #pragma unroll
      for (int nf = 0; nf < 6; nf++){
        const int nb = wn*48 + nf*8;
        b[nf][0] = __float_as_uint(Bs[k0+tig  ][nb+g]);
        b[nf][1] = __float_as_uint(Bs[k0+tig+4][nb+g]);
      }
      #pragma unroll
      for (int mf = 0; mf < 4; mf++)
        #pragma unroll
        for (int nf = 0; nf < 6; nf++)
          mma16n8k8(C[mf][nf], a[mf], b[nf]);
    }
    __syncthreads();
  }

  // Epilogue: q,k straight [t][h]; v transposed [b][h][t]
  const int bb = m0 >> 8;
  #pragma unroll
  for (int mf = 0; mf < 4; mf++){
    const int mlo = m0 + wm*64 + mf*16 + g;
    #pragma unroll
    for (int nf = 0; nf < 6; nf++){
      const int n = wn*48 + nf*8 + 2*tig;
      const int id = n >> 6, h = n & 63;
      if (id == 2){   // v -> g_vT[b][h][t]
        float* base = g_vT + (size_t)bb*16384;
        base[(h  )*256 + (mlo    & 255)] = C[mf][nf][0];
        base[(h+1)*256 + (mlo    & 255)] = C[mf][nf][1];
        base[(h  )*256 + ((mlo+8)& 255)] = C[mf][nf][2];
        base[(h+1)*256 + ((mlo+8)& 255)] = C[mf][nf][3];
      } else {
        float* dst = (id == 0) ? g_q : g_k;
        *(float2*)(dst + (size_t)(mlo    )*64 + h) = make_float2(C[mf][nf][0], C[mf][nf][1]);
        *(float2*)(dst + (size_t)(mlo + 8)*64 + h) = make_float2(C[mf][nf][2], C[mf][nf][3]);
      }
    }
  }
}

// ---------------- Tensor-core flash attention: one CTA per batch ----------------
// Warp w owns bands m0 = 16w and 240-16w (5 causal key-chunks each -> balanced).
// S = Q K^T via mma (K [t][h] is col-major B); softmax in C-frags (quad shuffles);
// P->A-frag via quad shuffle transpose; PV mma against Vt [h][t].
__global__ __launch_bounds__(256) void attn3(float* __restrict__ out){
  extern __shared__ float sm[];
  float* Qs  = sm;            // [256][68]  pitch 68 -> frag banks 4g+tig all-distinct
  float* Ks  = sm + 17408;    // [256][68]
  float* Vts = sm + 34816;    // [64][260]  pitch 260 -> same property
  const int b = blockIdx.x;
  const int tid = threadIdx.x, lane = tid & 31, w = tid >> 5;
  const int g = lane >> 2, tig = lane & 3;

  {
    const float4* Qg = (const float4*)(g_q  + (size_t)b*16384);
    const float4* Kg = (const float4*)(g_k  + (size_t)b*16384);
    const float4* Vg = (const float4*)(g_vT + (size_t)b*16384);
    #pragma unroll
    for (int it = 0; it < 16; it++){
      int i = tid + 256*it;
      float4 qv = Qg[i];
      qv.x = to_tf32(qv.x*0.125f); qv.y = to_tf32(qv.y*0.125f);   // fold H^-0.5
      qv.z = to_tf32(qv.z*0.125f); qv.w = to_tf32(qv.w*0.125f);
      *(float4*)(Qs + (i>>4)*68 + (i&15)*4) = qv;
      float4 kv = Kg[i];
      kv.x = to_tf32(kv.x); kv.y = to_tf32(kv.y);
      kv.z = to_tf32(kv.z); kv.w = to_tf32(kv.w);
      *(float4*)(Ks + (i>>4)*68 + (i&15)*4) = kv;
      float4 vv = Vg[i];
      vv.x = to_tf32(vv.x); vv.y = to_tf32(vv.y);
      vv.z = to_tf32(vv.z); vv.w = to_tf32(vv.w);
      *(float4*)(Vts + (i>>6)*260 + (i&63)*4) = vv;
    }
  }
  __syncthreads();

  #pragma unroll
  for (int bi = 0; bi < 2; bi++){
    const int m0 = bi ? (240 - 16*w) : 16*w;

    uint32_t aq[8][4];
    #pragma unroll
    for (int k = 0; k < 8; k++){
      aq[k][0] = __float_as_uint(Qs[(m0+g  )*68 + k*8 + tig  ]);
      aq[k][1] = __float_as_uint(Qs[(m0+g+8)*68 + k*8 + tig  ]);
      aq[k][2] = __float_as_uint(Qs[(m0+g  )*68 + k*8 + tig+4]);
      aq[k][3] = __float_as_uint(Qs[(m0+g+8)*68 + k*8 + tig+4]);
    }

    float O[8][4];
    #pragma unroll
    for (int jo = 0; jo < 8; jo++){ O[jo][0]=0.f; O[jo][1]=0.f; O[jo][2]=0.f; O[jo][3]=0.f; }
    float mr0 = -1e30f, mr1 = -1e30f, l0 = 0.f, l1 = 0.f;
    const int cd = m0 >> 6;

    for (int c = 0; c <= cd; c++){
      float S[8][4];
      #pragma unroll
      for (int j = 0; j < 8; j++){ S[j][0]=0.f; S[j][1]=0.f; S[j][2]=0.f; S[j][3]=0.f; }
      #pragma unroll
      for (int k = 0; k < 8; k++){
        #pragma unroll
        for (int j = 0; j < 8; j++){
          const float* kr = Ks + (c*64 + j*8 + g)*68 + k*8;
          uint32_t bf[2] = { __float_as_uint(kr[tig]), __float_as_uint(kr[tig+4]) };
          mma16n8k8(S[j], aq[k], bf);
        }
      }
      if (c == cd){   // diagonal chunk: causal mask
        #pragma unroll
        for (int j = 0; j < 8; j++){
          const int col = c*64 + j*8 + 2*tig;
          if (col     > m0+g  ) S[j][0] = -1e30f;
          if (col + 1 > m0+g  ) S[j][1] = -1e30f;
          if (col     > m0+g+8) S[j][2] = -1e30f;
          if (col + 1 > m0+g+8) S[j][3] = -1e30f;
        }
      }
      // chunk row max (rows g, g+8 live in this quad)
      float cm0 = -1e30f, cm1 = -1e30f;
      #pragma unroll
      for (int j = 0; j < 8; j++){
        cm0 = fmaxf(cm0, fmaxf(S[j][0], S[j][1]));
        cm1 = fmaxf(cm1, fmaxf(S[j][2], S[j][3]));
      }
      cm0 = fmaxf(cm0, __shfl_xor_sync(0xffffffffu, cm0, 1));
      cm0 = fmaxf(cm0, __shfl_xor_sync(0xffffffffu, cm0, 2));
      cm1 = fmaxf(cm1, __shfl_xor_sync(0xffffffffu, cm1, 1));
      cm1 = fmaxf(cm1, __shfl_xor_sync(0xffffffffu, cm1, 2));
      const float mn0 = fmaxf(mr0, cm0), mn1 = fmaxf(mr1, cm1);
      const float al0 = __expf(mr0 - mn0), al1 = __expf(mr1 - mn1);
      float s0 = 0.f, s1 = 0.f;
      #pragma unroll
      for (int j = 0; j < 8; j++){
        S[j][0] = __expf(S[j][0] - mn0); s0 += S[j][0];
        S[j][1] = __expf(S[j][1] - mn0); s0 += S[j][1];
        S[j][2] = __expf(S[j][2] - mn1); s1 += S[j][2];
        S[j][3] = __expf(S[j][3] - mn1); s1 += S[j][3];
      }
      s0 += __shfl_xor_sync(0xffffffffu, s0, 1);
      s0 += __shfl_xor_sync(0xffffffffu, s0, 2);
      s1 += __shfl_xor_sync(0xffffffffu, s1, 1);
      s1 += __shfl_xor_sync(0xffffffffu, s1, 2);
      l0 = l0*al0 + s0; l1 = l1*al1 + s1;
      mr0 = mn0; mr1 = mn1;
      #pragma unroll
      for (int jo = 0; jo < 8; jo++){
        O[jo][0] *= al0; O[jo][1] *= al0; O[jo][2] *= al1; O[jo][3] *= al1;
      }
      // PV: S n8-tile kk == P k8-tile kk; quad-shuffle C-frag -> A-frag
      const int src  = (lane & ~3) | (tig >> 1);
      const int src2 = src + 2;
      const bool odd = (tig & 1);
      #pragma unroll
      for (int kk = 0; kk < 8; kk++){
        float v0  = __shfl_sync(0xffffffffu, S[kk][0], src );
        float v1  = __shfl_sync(0xffffffffu, S[kk][1], src );
        float w0  = __shfl_sync(0xffffffffu, S[kk][2], src );
        float w1  = __shfl_sync(0xffffffffu, S[kk][3], src );
        float v0b = __shfl_sync(0xffffffffu, S[kk][0], src2);
        float v1b = __shfl_sync(0xffffffffu, S[kk][1], src2);
        float w0b = __shfl_sync(0xffffffffu, S[kk][2], src2);
        float w1b = __shfl_sync(0xffffffffu, S[kk][3], src2);
        uint32_t ap[4];
        ap[0] = __float_as_uint(to_tf32(odd ? v1  : v0 ));
        ap[1] = __float_as_uint(to_tf32(odd ? w1  : w0 ));
        ap[2] = __float_as_uint(to_tf32(odd ? v1b : v0b));
        ap[3] = __float_as_uint(to_tf32(odd ? w1b : w0b));
        #pragma unroll
        for (int jo = 0; jo < 8; jo++){
          const float* vr = Vts + (jo*8 + g)*260 + c*64 + kk*8;
          uint32_t bv[2] = { __float_as_uint(vr[tig]), __float_as_uint(vr[tig+4]) };
          mma16n8k8(O[jo], ap, bv);
        }
      }
    }

    const float inv0 = 1.0f / l0, inv1 = 1.0f / l1;
    float* ob = out + (size_t)b*16384;
    #pragma unroll
    for (int jo = 0; jo < 8; jo++){
      *(float2*)(ob + (m0+g  )*64 + jo*8 + 2*tig) = make_float2(O[jo][0]*inv0, O[jo][1]*inv0);
      *(float2*)(ob + (m0+g+8)*64 + jo*8 + 2*tig) = make_float2(O[jo][2]*inv1, O[jo][3]*inv1);
    }
  }
}

extern "C" void kernel_launch(void* const* d_in, const int* in_sizes, int n_in,
                              void* d_out, int out_size) {
  const float* x  = (const float*)d_in[0];
  const float* Wk = (const float*)d_in[1];
  const float* Wq = (const float*)d_in[2];
  const float* Wv = (const float*)d_in[3];
  float* out = (float*)d_out;
  (void)in_sizes; (void)n_in; (void)out_size;

  cudaFuncSetAttribute(attn3, cudaFuncAttributeMaxDynamicSharedMemorySize, 205824);

  wt_kernel<<<192, 128>>>(Wk, Wq, Wv);
  qkv_mma<<<1024, 256>>>(x);
  attn3<<<512, 256, 205824>>>(out);
}